// round 16
// baseline (speedup 1.0000x reference)
#include <cuda_runtime.h>
#include <cuda_bf16.h>
#include <math.h>
#include <stdint.h>

#define N_NODES 102400
#define N_EDGES 1638400
#define IN_DIM  16
#define GNN_H   64
#define GNN_HP  32             // packed bf16x2 pairs per GCN row
#define RNN_H   128
#define GATE4   512
#define GATE4P  256
#define OUT_DIM 7
#define SEQ_LEN 50
#define BATCH   (N_NODES / SEQ_LEN)   // 2048

#define SCAN_T  512
#define SCAN_NB (N_NODES / SCAN_T)    // 200

// ---------------------------------------------------------------------------
__device__ float g_dinv[N_NODES];
__device__ int   g_deg [N_NODES];     // zero-init at load; re-zeroed by k_gather_mm tail
__device__ int   g_cur [N_NODES];
__device__ int   g_off [N_NODES + 1];
__device__ int   g_boff[SCAN_NB];
__device__ int   g_csr_src[N_EDGES];
__device__ float g_csr_nrm[N_EDGES];
__device__ uint32_t g_xwP[N_NODES * GNN_HP];            // packed bf16x2 gcn_mm out (13MB)
__device__ uint32_t g_hP [N_NODES * GNN_HP];            // packed bf16x2 gather_mm out (13MB)
__device__ float g_xw  [N_NODES * GNN_H];               // fp32 final GCN out (GEMM A)
__device__ uint32_t g_pre [(size_t)N_NODES * GATE4P];   // bf16x2 packed, 105MB
__device__ float g_hseq[(size_t)N_NODES * RNN_H];
__device__ float g_hstate[BATCH * RNN_H];
__device__ float g_wihT0[GNN_H * GATE4];
__device__ float g_wihT1[RNN_H * GATE4];
__device__ uint32_t g_whhP0[(RNN_H / 2) * GATE4];
__device__ uint32_t g_whhP1[(RNN_H / 2) * GATE4];

// ---------------------------------------------------------------------------
__device__ __forceinline__ uint32_t cvt_tf32(float x) {
    uint32_t r; asm("cvt.rna.tf32.f32 %0, %1;" : "=r"(r) : "f"(x)); return r;
}
__device__ __forceinline__ uint32_t pack_bf16x2(float lo, float hi) {
    uint32_t r; asm("cvt.rn.bf16x2.f32 %0, %1, %2;" : "=r"(r) : "f"(hi), "f"(lo)); return r;
}
__device__ __forceinline__ float2 unpack_bf16x2(uint32_t u) {
    float2 r;
    r.x = __uint_as_float(u << 16);
    r.y = __uint_as_float(u & 0xffff0000u);
    return r;
}
__device__ __forceinline__ float tanh_fast(float x) {
    float y; asm("tanh.approx.f32 %0, %1;" : "=f"(y) : "f"(x)); return y;
}
__device__ __forceinline__ float sigmoid_fast(float x) {
    return 0.5f * tanh_fast(0.5f * x) + 0.5f;
}
__device__ __forceinline__ void mma_tf32(float& d0, float& d1, float& d2, float& d3,
                                         uint32_t a0, uint32_t a1, uint32_t a2, uint32_t a3,
                                         uint32_t b0, uint32_t b1) {
    asm volatile("mma.sync.aligned.m16n8k8.row.col.f32.tf32.tf32.f32 "
                 "{%0,%1,%2,%3}, {%4,%5,%6,%7}, {%8,%9}, {%0,%1,%2,%3};"
                 : "+f"(d0), "+f"(d1), "+f"(d2), "+f"(d3)
                 : "r"(a0), "r"(a1), "r"(a2), "r"(a3), "r"(b0), "r"(b1));
}
__device__ __forceinline__ void mma_bf16(float& d0, float& d1, float& d2, float& d3,
                                         uint32_t a0, uint32_t a1, uint32_t a2, uint32_t a3,
                                         uint32_t b0, uint32_t b1) {
    asm volatile("mma.sync.aligned.m16n8k16.row.col.f32.bf16.bf16.f32 "
                 "{%0,%1,%2,%3}, {%4,%5,%6,%7}, {%8,%9}, {%0,%1,%2,%3};"
                 : "+f"(d0), "+f"(d1), "+f"(d2), "+f"(d3)
                 : "r"(a0), "r"(a1), "r"(a2), "r"(a3), "r"(b0), "r"(b1));
}
#define CP_ASYNC16(dst, src) \
    asm volatile("cp.async.cg.shared.global [%0], [%1], 16;" :: "r"(dst), "l"(src))
#define CP_COMMIT() asm volatile("cp.async.commit_group;")
#define CP_WAIT0()  asm volatile("cp.async.wait_group 0;" ::: "memory")

// ---------------------------------------------------------------------------
// CSR build
// ---------------------------------------------------------------------------
__global__ void k_deg_int(const int* __restrict__ ei, int* __restrict__ deg) {
    int e = blockIdx.x * blockDim.x + threadIdx.x;
    if (e >= N_EDGES) return;
    atomicAdd(&deg[ei[N_EDGES + e]], 1);
}
__global__ __launch_bounds__(SCAN_T) void k_dinv_bsum(const int* __restrict__ deg,
                                                      float* __restrict__ dinv,
                                                      int* __restrict__ bsum) {
    __shared__ int s[SCAN_T];
    int i = threadIdx.x;
    int g = blockIdx.x * SCAN_T + i;
    int d = deg[g];
    dinv[g] = rsqrtf((float)(d + 1));
    s[i] = d;
    __syncthreads();
    for (int k = SCAN_T / 2; k > 0; k >>= 1) {
        if (i < k) s[i] += s[i + k];
        __syncthreads();
    }
    if (i == 0) bsum[blockIdx.x] = s[0];
}
__global__ __launch_bounds__(SCAN_T) void k_scan_write2(const int* __restrict__ deg,
                                                        const int* __restrict__ bsum,
                                                        int* __restrict__ off) {
    __shared__ int s[SCAN_T];
    __shared__ int sboff;
    int i = threadIdx.x;
    int b = blockIdx.x;
    int g = b * SCAN_T + i;
    if (i < 32) {
        int p = 0;
        for (int j = i; j < b; j += 32) p += bsum[j];
#pragma unroll
        for (int o = 16; o > 0; o >>= 1) p += __shfl_down_sync(0xffffffffu, p, o);
        if (i == 0) sboff = p;
    }
    int my = deg[g];
    s[i] = my;
    __syncthreads();
    for (int d = 1; d < SCAN_T; d <<= 1) {
        int v = (i >= d) ? s[i - d] : 0;
        __syncthreads();
        s[i] += v;
        __syncthreads();
    }
    off[g] = sboff + s[i] - my;
    if (b == 0 && i == 0) off[N_NODES] = N_EDGES;
}
__global__ void k_csr_fill(const int* __restrict__ ei, const int* __restrict__ off,
                           int* __restrict__ cur, const float* __restrict__ dinv,
                           int* __restrict__ csr_src, float* __restrict__ csr_nrm) {
    int e = blockIdx.x * blockDim.x + threadIdx.x;
    if (e >= N_EDGES) return;
    int s = ei[e];
    int d = ei[N_EDGES + e];
    int pos = off[d] + atomicAdd(&cur[d], 1);
    csr_src[pos] = s;
    csr_nrm[pos] = dinv[s] * dinv[d];
}

// ---------------------------------------------------------------------------
// GCN layer-1 dense part -> packed bf16x2 output
// ---------------------------------------------------------------------------
__global__ __launch_bounds__(512) void k_gcn_mm_p(const float* __restrict__ X,
                                                  const float* __restrict__ W,
                                                  uint32_t* __restrict__ outP) {
    __shared__ float sW[IN_DIM * 64];
    __shared__ float sX[16 * IN_DIM];
    int tid = threadIdx.x;
    size_t row0 = (size_t)blockIdx.x * 16;
    for (int i = tid; i < IN_DIM * 64; i += 512) sW[i] = W[i];
    if (tid < 16 * IN_DIM) sX[tid] = X[row0 * IN_DIM + tid];
    __syncthreads();
    int r  = tid >> 5;
    int cp = tid & 31;
    int c  = cp * 2;
    float a0 = 0.f, a1 = 0.f;
#pragma unroll
    for (int k = 0; k < IN_DIM; ++k) {
        float xv = sX[r * IN_DIM + k];
        a0 = fmaf(xv, sW[k * 64 + c],     a0);
        a1 = fmaf(xv, sW[k * 64 + c + 1], a1);
    }
    outP[(row0 + r) * GNN_HP + cp] = pack_bf16x2(a0, a1);
}

// ---------------------------------------------------------------------------
// Fused gather(bf16 xwP) + relu + @w2 -> PACKED bf16 output hP.
// 512 threads; warp handles 2 nodes. Tail re-zeros deg/cur.
// ---------------------------------------------------------------------------
__global__ __launch_bounds__(512) void k_gather_mm(const int* __restrict__ off,
                                                   const int* __restrict__ csr_src,
                                                   const float* __restrict__ csr_nrm,
                                                   const uint32_t* __restrict__ xwP,
                                                   const float* __restrict__ dinv,
                                                   const float* __restrict__ b1,
                                                   const float* __restrict__ w2,
                                                   uint32_t* __restrict__ outP,
                                                   int* __restrict__ deg_z,
                                                   int* __restrict__ cur_z) {
    __shared__ float sw[64 * 64];
    __shared__ float sv[32][66];
    int tid = threadIdx.x;
    for (int i = tid; i < 64 * 64; i += 512) sw[i] = w2[i];
    int warp = tid >> 5;
    int lane = tid & 31;
    int c0 = lane * 2;
    float2 bb = *(const float2*)&b1[c0];
#pragma unroll
    for (int half = 0; half < 2; ++half) {
        int d = blockIdx.x * 32 + half * 16 + warp;
        float dv = dinv[d];
        float2 self = unpack_bf16x2(xwP[(size_t)d * GNN_HP + lane]);
        float accx = self.x * dv * dv + bb.x;
        float accy = self.y * dv * dv + bb.y;
        int e0 = off[d], e1 = off[d + 1];
        for (int e = e0; e < e1; ++e) {
            int   s   = csr_src[e];
            float nrm = csr_nrm[e];
            float2 v = unpack_bf16x2(xwP[(size_t)s * GNN_HP + lane]);
            accx = fmaf(v.x, nrm, accx);
            accy = fmaf(v.y, nrm, accy);
        }
        sv[half * 16 + warp][c0]     = fmaxf(accx, 0.f);
        sv[half * 16 + warp][c0 + 1] = fmaxf(accy, 0.f);
    }
    __syncthreads();
#pragma unroll
    for (int half = 0; half < 2; ++half) {
        int r = half * 16 + warp;
        int d = blockIdx.x * 32 + r;
        float ox = 0.f, oy = 0.f;
#pragma unroll
        for (int k = 0; k < 64; ++k) {
            float a = sv[r][k];
            float2 wv = *(const float2*)&sw[k * 64 + c0];
            ox = fmaf(a, wv.x, ox);
            oy = fmaf(a, wv.y, oy);
        }
        outP[(size_t)d * GNN_HP + lane] = pack_bf16x2(ox, oy);
    }
    int zt = blockIdx.x * 512 + tid;
    if (zt < N_NODES) { deg_z[zt] = 0; cur_z[zt] = 0; }
}

// ---------------------------------------------------------------------------
// Gather layer 2: reads packed bf16 hP, writes fp32 xw (GEMM A operand)
// ---------------------------------------------------------------------------
__global__ __launch_bounds__(256) void k_gather_p(const int* __restrict__ off,
                                                  const int* __restrict__ csr_src,
                                                  const float* __restrict__ csr_nrm,
                                                  const uint32_t* __restrict__ hP,
                                                  const float* __restrict__ dinv,
                                                  const float* __restrict__ bias,
                                                  float* __restrict__ out) {
    int warp = (blockIdx.x * 256 + threadIdx.x) >> 5;
    int lane = threadIdx.x & 31;
    if (warp >= N_NODES) return;
    int d = warp;
    int c0 = lane * 2;
    float dv = dinv[d];
    float2 self = unpack_bf16x2(hP[(size_t)d * GNN_HP + lane]);
    float2 bb   = *(const float2*)&bias[c0];
    float accx = self.x * dv * dv + bb.x;
    float accy = self.y * dv * dv + bb.y;
    int e0 = off[d], e1 = off[d + 1];
    for (int e = e0; e < e1; ++e) {
        int   s   = csr_src[e];
        float nrm = csr_nrm[e];
        float2 v = unpack_bf16x2(hP[(size_t)s * GNN_HP + lane]);
        accx = fmaf(v.x, nrm, accx);
        accy = fmaf(v.y, nrm, accy);
    }
    float2 o; o.x = fmaxf(accx, 0.f); o.y = fmaxf(accy, 0.f);
    *(float2*)&out[(size_t)d * 64 + c0] = o;
}

// ---------------------------------------------------------------------------
// transpose with tf32 rounding
// ---------------------------------------------------------------------------
__global__ void k_transpose_tf32(const float* __restrict__ in, float* __restrict__ out,
                                 int R, int C) {
    int i = blockIdx.x * blockDim.x + threadIdx.x;
    if (i >= R * C) return;
    int r = i / C, c = i % C;
    out[c * R + r] = __uint_as_float(cvt_tf32(in[i]));
}

// whh [512,128] -> packed bf16x2 [64 kpairs][512 cols]
__global__ void k_pack_whh(const float* __restrict__ whh, uint32_t* __restrict__ out) {
    int i = blockIdx.x * blockDim.x + threadIdx.x;
    if (i >= (RNN_H / 2) * GATE4) return;
    int kp = i >> 9, col = i & 511;
    float lo = whh[col * RNN_H + 2 * kp];
    float hi = whh[col * RNN_H + 2 * kp + 1];
    out[i] = pack_bf16x2(lo, hi);
}

// ---------------------------------------------------------------------------
// tf32 GEMM: C[M, 256 packed] = bf16x2( A[M,K] @ Bt[K,512] + b1 + b2 )
// ---------------------------------------------------------------------------
__global__ __launch_bounds__(256) void k_gemm_tf32(const float* __restrict__ A,
                                                   const float* __restrict__ Bt,
                                                   const float* __restrict__ b1,
                                                   const float* __restrict__ b2,
                                                   uint32_t* __restrict__ C, int K) {
    __shared__ uint32_t As[16][72];
    __shared__ uint32_t Bs[16][136];
    int tid = threadIdx.x;
    int w = tid >> 5, lane = tid & 31;
    int mw = (w >> 2) * 32;
    int nw = (w & 3) * 32;
    int g = lane >> 2, t = lane & 3;
    size_t bm = (size_t)blockIdx.x * 64;
    int bn = blockIdx.y * 128;

    float acc[2][4][4];
#pragma unroll
    for (int mt = 0; mt < 2; ++mt)
#pragma unroll
        for (int nt = 0; nt < 4; ++nt)
#pragma unroll
            for (int i = 0; i < 4; ++i) acc[mt][nt][i] = 0.f;

    int ar = tid >> 2, ac = (tid & 3) * 4;
    int brw = tid >> 5, bcf = tid & 31;

    for (int k0 = 0; k0 < K; k0 += 16) {
        float4 av = *(const float4*)(A + (bm + ar) * K + k0 + ac);
        float4 bq0 = *(const float4*)(Bt + (size_t)(k0 + brw) * GATE4 + bn + bcf * 4);
        float4 bq1 = *(const float4*)(Bt + (size_t)(k0 + 8 + brw) * GATE4 + bn + bcf * 4);
        __syncthreads();
        As[ac + 0][ar] = cvt_tf32(av.x);
        As[ac + 1][ar] = cvt_tf32(av.y);
        As[ac + 2][ar] = cvt_tf32(av.z);
        As[ac + 3][ar] = cvt_tf32(av.w);
        {
            uint32_t* d0 = &Bs[brw][bcf * 4];
            d0[0] = __float_as_uint(bq0.x); d0[1] = __float_as_uint(bq0.y);
            d0[2] = __float_as_uint(bq0.z); d0[3] = __float_as_uint(bq0.w);
            uint32_t* d1 = &Bs[brw + 8][bcf * 4];
            d1[0] = __float_as_uint(bq1.x); d1[1] = __float_as_uint(bq1.y);
            d1[2] = __float_as_uint(bq1.z); d1[3] = __float_as_uint(bq1.w);
        }
        __syncthreads();
#pragma unroll
        for (int kt = 0; kt < 2; ++kt) {
            uint32_t af[2][4];
#pragma unroll
            for (int mt = 0; mt < 2; ++mt) {
                int mrow = mw + mt * 16 + g;
                af[mt][0] = As[kt * 8 + t][mrow];
                af[mt][1] = As[kt * 8 + t][mrow + 8];
                af[mt][2] = As[kt * 8 + t + 4][mrow];
                af[mt][3] = As[kt * 8 + t + 4][mrow + 8];
            }
#pragma unroll
            for (int nt = 0; nt < 4; ++nt) {
                int ncol = nw + nt * 8 + g;
                uint32_t bf0 = Bs[kt * 8 + t][ncol];
                uint32_t bf1 = Bs[kt * 8 + t + 4][ncol];
#pragma unroll
                for (int mt = 0; mt < 2; ++mt)
                    mma_tf32(acc[mt][nt][0], acc[mt][nt][1], acc[mt][nt][2], acc[mt][nt][3],
                             af[mt][0], af[mt][1], af[mt][2], af[mt][3], bf0, bf1);
            }
        }
    }
#pragma unroll
    for (int nt = 0; nt < 4; ++nt) {
        int c0 = bn + nw + nt * 8 + 2 * t;
        int jp = c0 >> 1;
        float bb0 = b1[c0] + b2[c0];
        float bb1 = b1[c0 + 1] + b2[c0 + 1];
#pragma unroll
        for (int mt = 0; mt < 2; ++mt) {
            size_t r0 = bm + mw + mt * 16 + g;
            C[r0 * GATE4P + jp]       = pack_bf16x2(acc[mt][nt][0] + bb0, acc[mt][nt][1] + bb1);
            C[(r0 + 8) * GATE4P + jp] = pack_bf16x2(acc[mt][nt][2] + bb0, acc[mt][nt][3] + bb1);
        }
    }
}

// ---------------------------------------------------------------------------
// Persistent bf16-mma LSTM, resident weights, packed bf16 pre, pipelined loads.
// 128 blocks x 512 threads, SBM=16.
// ---------------------------------------------------------------------------
#define L_SBM 16
#define L_NBLK (BATCH / L_SBM)     // 128
#define SH2 68
#define BSP 520
#define L_SMEM ((L_SBM * SH2 + 64 * BSP) * 4)   // 137,472 B

__global__ __launch_bounds__(512, 1) void k_lstm_mma(const uint32_t* __restrict__ pre,
                                                     const uint32_t* __restrict__ whhP,
                                                     float* __restrict__ hseq,
                                                     float* __restrict__ hlast) {
    extern __shared__ uint32_t smem[];
    uint32_t* sh = smem;
    uint32_t* Bs = smem + L_SBM * SH2;
    int tid = threadIdx.x;
    int w = tid >> 5, lane = tid & 31;
    int q = w;
    int g = lane >> 2, t = lane & 3;
    int b0 = blockIdx.x * L_SBM;

    uint32_t bs0 = (uint32_t)__cvta_generic_to_shared(Bs);

#pragma unroll
    for (int it = 0; it < 16; ++it) {
        int fid = it * 512 + tid;
        int row = fid >> 7, colf = fid & 127;
        CP_ASYNC16(bs0 + (uint32_t)(row * BSP + colf * 4) * 4,
                   whhP + (size_t)row * GATE4 + colf * 4);
    }
    CP_COMMIT();

    size_t preoff[8];
#pragma unroll
    for (int gate = 0; gate < 4; ++gate) {
        int jp = gate * 64 + q * 4 + t;
        preoff[gate * 2 + 0] = (size_t)(b0 + g) * SEQ_LEN * GATE4P + jp;
        preoff[gate * 2 + 1] = (size_t)(b0 + g + 8) * SEQ_LEN * GATE4P + jp;
    }

    float c[4];
#pragma unroll
    for (int i = 0; i < 4; ++i) c[i] = 0.f;
    for (int i = tid; i < L_SBM * SH2; i += 512) sh[i] = 0u;

    uint32_t pr[8];
#pragma unroll
    for (int i = 0; i < 8; ++i) pr[i] = pre[preoff[i]];

    CP_WAIT0();
    __syncthreads();

    for (int st = 0; st < SEQ_LEN; ++st) {
        float acc[4][4];
#pragma unroll
        for (int gate = 0; gate < 4; ++gate) {
            float2 p0 = unpack_bf16x2(pr[gate * 2 + 0]);
            float2 p1 = unpack_bf16x2(pr[gate * 2 + 1]);
            acc[gate][0] = p0.x; acc[gate][1] = p0.y;
            acc[gate][2] = p1.x; acc[gate][3] = p1.y;
        }
        if (st + 1 < SEQ_LEN) {
            size_t so = (size_t)(st + 1) * GATE4P;
#pragma unroll
            for (int i = 0; i < 8; ++i) pr[i] = pre[preoff[i] + so];
        }
#pragma unroll
        for (int kt = 0; kt < 8; ++kt) {
            int kp = kt * 8;
            uint32_t a0 = sh[g * SH2 + kp + t];
            uint32_t a1 = sh[(g + 8) * SH2 + kp + t];
            uint32_t a2 = sh[g * SH2 + kp + t + 4];
            uint32_t a3 = sh[(g + 8) * SH2 + kp + t + 4];
#pragma unroll
            for (int gate = 0; gate < 4; ++gate) {
                int colg = gate * 128 + q * 8 + g;
                uint32_t bf0 = Bs[(kp + t) * BSP + colg];
                uint32_t bf1 = Bs[(kp + t + 4) * BSP + colg];
                mma_bf16(acc[gate][0], acc[gate][1], acc[gate][2], acc[gate][3],
                         a0, a1, a2, a3, bf0, bf1);
            }
        }
        __syncthreads();
        float hv[4];
#pragma unroll
        for (int p = 0; p < 4; ++p) {
            float ig = sigmoid_fast(acc[0][p]);
            float fg = sigmoid_fast(acc[1][p]);
            float gg = tanh_fast(acc[2][p]);
            float og = sigmoid_fast(acc[3][p]);
            float cc = fg * c[p] + ig * gg;
            hv[p] = og * tanh_fast(cc);
            c[p] = cc;
        }
        int jp = q * 4 + t;
        sh[g * SH2 + jp]       = pack_bf16x2(hv[0], hv[1]);
        sh[(g + 8) * SH2 + jp] = pack_bf16x2(hv[2], hv[3]);
        int j0 = q * 8 + 2 * t;
        if (hseq) {
            float2 v0; v0.x = hv[0]; v0.y = hv[1];
            float2 v1; v1.x = hv[2]; v1.y = hv[3];
            *(float2*)(hseq + ((size_t)(b0 + g) * SEQ_LEN + st) * RNN_H + j0)     = v0;
            *(float2*)(hseq + ((size_t)(b0 + g + 8) * SEQ_LEN + st) * RNN_H + j0) = v1;
        }
        if (st == SEQ_LEN - 1) {
            float2 v0; v0.x = hv[0]; v0.y = hv[1];
            float2 v1; v1.x = hv[2]; v1.y = hv[3];
            *(float2*)(hlast + (b0 + g) * RNN_H + j0)     = v0;
            *(float2*)(hlast + (b0 + g + 8) * RNN_H + j0) = v1;
        }
        __syncthreads();
    }
}

// ---------------------------------------------------------------------------
// FC head
// ---------------------------------------------------------------------------
__global__ void k_fc(const float* __restrict__ h, const float* __restrict__ w,
                     const float* __restrict__ b, float* __restrict__ out) {
    int i = blockIdx.x * blockDim.x + threadIdx.x;
    if (i >= BATCH * OUT_DIM) return;
    int bb = i / OUT_DIM, o = i % OUT_DIM;
    float acc = b[o];
#pragma unroll 4
    for (int k = 0; k < RNN_H; ++k)
        acc = fmaf(h[bb * RNN_H + k], w[k * OUT_DIM + o], acc);
    out[i] = acc;
}

// ---------------------------------------------------------------------------
// Host launcher
// ---------------------------------------------------------------------------
extern "C" void kernel_launch(void* const* d_in, const int* in_sizes, int n_in,
                              void* d_out, int out_size) {
    const float* x  = (const float*)d_in[0];
    const int*   ei = (const int*)d_in[1];
    int w1i = n_in - 14;
    const float* w1   = (const float*)d_in[w1i + 0];
    const float* b1   = (const float*)d_in[w1i + 1];
    const float* w2   = (const float*)d_in[w1i + 2];
    const float* b2   = (const float*)d_in[w1i + 3];
    const float* wih0 = (const float*)d_in[w1i + 4];
    const float* whh0 = (const float*)d_in[w1i + 5];
    const float* bih0 = (const float*)d_in[w1i + 6];
    const float* bhh0 = (const float*)d_in[w1i + 7];
    const float* wih1 = (const float*)d_in[w1i + 8];
    const float* whh1 = (const float*)d_in[w1i + 9];
    const float* bih1 = (const float*)d_in[w1i + 10];
    const float* bhh1 = (const float*)d_in[w1i + 11];
    const float* fcw  = (const float*)d_in[w1i + 12];
    const float* fcb  = (const float*)d_in[w1i + 13];
    float* out = (float*)d_out;

    float *dinv, *xw, *hseq, *hstate, *csr_nrm;
    float *wihT0, *wihT1;
    uint32_t *xwP, *hP, *pre, *whhP0, *whhP1;
    int *deg, *cur, *off, *boff, *csr_src;
    cudaGetSymbolAddress((void**)&dinv,    g_dinv);
    cudaGetSymbolAddress((void**)&deg,     g_deg);
    cudaGetSymbolAddress((void**)&cur,     g_cur);
    cudaGetSymbolAddress((void**)&off,     g_off);
    cudaGetSymbolAddress((void**)&boff,    g_boff);
    cudaGetSymbolAddress((void**)&csr_src, g_csr_src);
    cudaGetSymbolAddress((void**)&csr_nrm, g_csr_nrm);
    cudaGetSymbolAddress((void**)&xwP,     g_xwP);
    cudaGetSymbolAddress((void**)&hP,      g_hP);
    cudaGetSymbolAddress((void**)&xw,      g_xw);
    cudaGetSymbolAddress((void**)&pre,     g_pre);
    cudaGetSymbolAddress((void**)&hseq,    g_hseq);
    cudaGetSymbolAddress((void**)&hstate,  g_hstate);
    cudaGetSymbolAddress((void**)&wihT0,   g_wihT0);
    cudaGetSymbolAddress((void**)&wihT1,   g_wihT1);
    cudaGetSymbolAddress((void**)&whhP0,   g_whhP0);
    cudaGetSymbolAddress((void**)&whhP1,   g_whhP1);

    static cudaStream_t s1 = nullptr;
    static cudaEvent_t evFork = nullptr, evCsr = nullptr, evT = nullptr;
    static bool init_done = false;
    if (!init_done) {
        cudaFuncSetAttribute(k_lstm_mma, cudaFuncAttributeMaxDynamicSharedMemorySize, L_SMEM);
        cudaStreamCreateWithFlags(&s1, cudaStreamNonBlocking);
        cudaEventCreateWithFlags(&evFork, cudaEventDisableTiming);
        cudaEventCreateWithFlags(&evCsr,  cudaEventDisableTiming);
        cudaEventCreateWithFlags(&evT,    cudaEventDisableTiming);
        init_done = true;
    }

    const int T = 256;

    // --- fork: CSR chain on s1 ---
    cudaEventRecord(evFork, 0);
    cudaStreamWaitEvent(s1, evFork, 0);
    k_deg_int<<<(N_EDGES + T - 1) / T, T, 0, s1>>>(ei, deg);
    k_dinv_bsum<<<SCAN_NB, SCAN_T, 0, s1>>>(deg, dinv, boff);
    k_scan_write2<<<SCAN_NB, SCAN_T, 0, s1>>>(deg, boff, off);
    k_csr_fill<<<(N_EDGES + T - 1) / T, T, 0, s1>>>(ei, off, cur, dinv, csr_src, csr_nrm);
    cudaEventRecord(evCsr, s1);

    // --- main: dense part of GCN layer 1 (packed bf16 out) ---
    k_gcn_mm_p<<<N_NODES / 16, 512>>>(x, w1, xwP);

    // --- join, then gathers ---
    cudaStreamWaitEvent(0, evCsr, 0);
    k_gather_mm<<<N_NODES / 32, 512>>>(off, csr_src, csr_nrm, xwP, dinv, b1, w2, hP,
                                       deg, cur);
    k_gather_p<<<N_NODES / 8, 256>>>(off, csr_src, csr_nrm, hP, dinv, b2, xw);

    // --- weight prep on s1 (overlaps gathers) ---
    k_transpose_tf32<<<(GATE4 * GNN_H + T - 1) / T, T, 0, s1>>>(wih0, wihT0, GATE4, GNN_H);
    k_transpose_tf32<<<(GATE4 * RNN_H + T - 1) / T, T, 0, s1>>>(wih1, wihT1, GATE4, RNN_H);
    k_pack_whh<<<((RNN_H / 2) * GATE4 + T - 1) / T, T, 0, s1>>>(whh0, whhP0);
    k_pack_whh<<<((RNN_H / 2) * GATE4 + T - 1) / T, T, 0, s1>>>(whh1, whhP1);
    cudaEventRecord(evT, s1);
    cudaStreamWaitEvent(0, evT, 0);

    // --- LSTM layer 0 ---
    {
        dim3 grid(N_NODES / 64, GATE4 / 128);
        k_gemm_tf32<<<grid, 256>>>(xw, wihT0, bih0, bhh0, pre, GNN_H);
    }
    k_lstm_mma<<<L_NBLK, 512, L_SMEM>>>(pre, whhP0, hseq, hstate);

    // --- LSTM layer 1 ---
    {
        dim3 grid(N_NODES / 64, GATE4 / 128);
        k_gemm_tf32<<<grid, 256>>>(hseq, wihT1, bih1, bhh1, pre, RNN_H);
    }
    k_lstm_mma<<<L_NBLK, 512, L_SMEM>>>(pre, whhP1, (float*)nullptr, hstate);

    // --- FC head ---
    k_fc<<<(BATCH * OUT_DIM + T - 1) / T, T>>>(hstate, fcw, fcb, out);
}

// round 17
// speedup vs baseline: 1.0131x; 1.0131x over previous
#include <cuda_runtime.h>
#include <cuda_bf16.h>
#include <math.h>
#include <stdint.h>

#define N_NODES 102400
#define N_EDGES 1638400
#define IN_DIM  16
#define GNN_H   64
#define GNN_HP  32             // packed bf16x2 pairs per GCN row
#define RNN_H   128
#define GATE4   512
#define GATE4P  256
#define OUT_DIM 7
#define SEQ_LEN 50
#define BATCH   (N_NODES / SEQ_LEN)   // 2048

#define SCAN_T  512
#define SCAN_NB (N_NODES / SCAN_T)    // 200

// ---------------------------------------------------------------------------
__device__ float g_dinv[N_NODES];
__device__ int   g_deg [N_NODES];     // zero-init at load; re-zeroed by k_gather_mm tail
__device__ int   g_cur [N_NODES];
__device__ int   g_off [N_NODES + 1];
__device__ int   g_boff[SCAN_NB];
__device__ int2  g_csr [N_EDGES];                       // {src, nrm bits} interleaved
__device__ uint32_t g_xwP[N_NODES * GNN_HP];            // packed bf16x2 gcn_mm out (13MB)
__device__ uint32_t g_hP [N_NODES * GNN_HP];            // packed bf16x2 gather_mm out (13MB)
__device__ float g_xw  [N_NODES * GNN_H];               // fp32 final GCN out (GEMM A)
__device__ uint32_t g_pre [(size_t)N_NODES * GATE4P];   // bf16x2 packed, 105MB
__device__ float g_hseq[(size_t)N_NODES * RNN_H];
__device__ float g_hstate[BATCH * RNN_H];
__device__ float g_wihT0[GNN_H * GATE4];
__device__ float g_wihT1[RNN_H * GATE4];
__device__ uint32_t g_whhP0[(RNN_H / 2) * GATE4];
__device__ uint32_t g_whhP1[(RNN_H / 2) * GATE4];

// ---------------------------------------------------------------------------
__device__ __forceinline__ uint32_t cvt_tf32(float x) {
    uint32_t r; asm("cvt.rna.tf32.f32 %0, %1;" : "=r"(r) : "f"(x)); return r;
}
__device__ __forceinline__ uint32_t pack_bf16x2(float lo, float hi) {
    uint32_t r; asm("cvt.rn.bf16x2.f32 %0, %1, %2;" : "=r"(r) : "f"(hi), "f"(lo)); return r;
}
__device__ __forceinline__ float2 unpack_bf16x2(uint32_t u) {
    float2 r;
    r.x = __uint_as_float(u << 16);
    r.y = __uint_as_float(u & 0xffff0000u);
    return r;
}
__device__ __forceinline__ float tanh_fast(float x) {
    float y; asm("tanh.approx.f32 %0, %1;" : "=f"(y) : "f"(x)); return y;
}
__device__ __forceinline__ float sigmoid_fast(float x) {
    return 0.5f * tanh_fast(0.5f * x) + 0.5f;
}
__device__ __forceinline__ void mma_tf32(float& d0, float& d1, float& d2, float& d3,
                                         uint32_t a0, uint32_t a1, uint32_t a2, uint32_t a3,
                                         uint32_t b0, uint32_t b1) {
    asm volatile("mma.sync.aligned.m16n8k8.row.col.f32.tf32.tf32.f32 "
                 "{%0,%1,%2,%3}, {%4,%5,%6,%7}, {%8,%9}, {%0,%1,%2,%3};"
                 : "+f"(d0), "+f"(d1), "+f"(d2), "+f"(d3)
                 : "r"(a0), "r"(a1), "r"(a2), "r"(a3), "r"(b0), "r"(b1));
}
__device__ __forceinline__ void mma_bf16(float& d0, float& d1, float& d2, float& d3,
                                         uint32_t a0, uint32_t a1, uint32_t a2, uint32_t a3,
                                         uint32_t b0, uint32_t b1) {
    asm volatile("mma.sync.aligned.m16n8k16.row.col.f32.bf16.bf16.f32 "
                 "{%0,%1,%2,%3}, {%4,%5,%6,%7}, {%8,%9}, {%0,%1,%2,%3};"
                 : "+f"(d0), "+f"(d1), "+f"(d2), "+f"(d3)
                 : "r"(a0), "r"(a1), "r"(a2), "r"(a3), "r"(b0), "r"(b1));
}
#define CP_ASYNC16(dst, src) \
    asm volatile("cp.async.cg.shared.global [%0], [%1], 16;" :: "r"(dst), "l"(src))
#define CP_COMMIT() asm volatile("cp.async.commit_group;")
#define CP_WAIT0()  asm volatile("cp.async.wait_group 0;" ::: "memory")

// ---------------------------------------------------------------------------
// CSR build
// ---------------------------------------------------------------------------
__global__ void k_deg_int(const int* __restrict__ ei, int* __restrict__ deg) {
    int e = blockIdx.x * blockDim.x + threadIdx.x;
    if (e >= N_EDGES) return;
    atomicAdd(&deg[ei[N_EDGES + e]], 1);
}
__global__ __launch_bounds__(SCAN_T) void k_dinv_bsum(const int* __restrict__ deg,
                                                      float* __restrict__ dinv,
                                                      int* __restrict__ bsum) {
    __shared__ int s[SCAN_T];
    int i = threadIdx.x;
    int g = blockIdx.x * SCAN_T + i;
    int d = deg[g];
    dinv[g] = rsqrtf((float)(d + 1));
    s[i] = d;
    __syncthreads();
    for (int k = SCAN_T / 2; k > 0; k >>= 1) {
        if (i < k) s[i] += s[i + k];
        __syncthreads();
    }
    if (i == 0) bsum[blockIdx.x] = s[0];
}
__global__ __launch_bounds__(SCAN_T) void k_scan_write2(const int* __restrict__ deg,
                                                        const int* __restrict__ bsum,
                                                        int* __restrict__ off) {
    __shared__ int s[SCAN_T];
    __shared__ int sboff;
    int i = threadIdx.x;
    int b = blockIdx.x;
    int g = b * SCAN_T + i;
    if (i < 32) {
        int p = 0;
        for (int j = i; j < b; j += 32) p += bsum[j];
#pragma unroll
        for (int o = 16; o > 0; o >>= 1) p += __shfl_down_sync(0xffffffffu, p, o);
        if (i == 0) sboff = p;
    }
    int my = deg[g];
    s[i] = my;
    __syncthreads();
    for (int d = 1; d < SCAN_T; d <<= 1) {
        int v = (i >= d) ? s[i - d] : 0;
        __syncthreads();
        s[i] += v;
        __syncthreads();
    }
    off[g] = sboff + s[i] - my;
    if (b == 0 && i == 0) off[N_NODES] = N_EDGES;
}
__global__ void k_csr_fill(const int* __restrict__ ei, const int* __restrict__ off,
                           int* __restrict__ cur, const float* __restrict__ dinv,
                           int2* __restrict__ csr) {
    int e = blockIdx.x * blockDim.x + threadIdx.x;
    if (e >= N_EDGES) return;
    int s = ei[e];
    int d = ei[N_EDGES + e];
    int pos = off[d] + atomicAdd(&cur[d], 1);
    int2 rec;
    rec.x = s;
    rec.y = __float_as_int(dinv[s] * dinv[d]);
    csr[pos] = rec;
}

// ---------------------------------------------------------------------------
// GCN layer-1 dense part -> packed bf16x2 output
// ---------------------------------------------------------------------------
__global__ __launch_bounds__(512) void k_gcn_mm_p(const float* __restrict__ X,
                                                  const float* __restrict__ W,
                                                  uint32_t* __restrict__ outP) {
    __shared__ float sW[IN_DIM * 64];
    __shared__ float sX[16 * IN_DIM];
    int tid = threadIdx.x;
    size_t row0 = (size_t)blockIdx.x * 16;
    for (int i = tid; i < IN_DIM * 64; i += 512) sW[i] = W[i];
    if (tid < 16 * IN_DIM) sX[tid] = X[row0 * IN_DIM + tid];
    __syncthreads();
    int r  = tid >> 5;
    int cp = tid & 31;
    int c  = cp * 2;
    float a0 = 0.f, a1 = 0.f;
#pragma unroll
    for (int k = 0; k < IN_DIM; ++k) {
        float xv = sX[r * IN_DIM + k];
        a0 = fmaf(xv, sW[k * 64 + c],     a0);
        a1 = fmaf(xv, sW[k * 64 + c + 1], a1);
    }
    outP[(row0 + r) * GNN_HP + cp] = pack_bf16x2(a0, a1);
}

// ---------------------------------------------------------------------------
// Fused gather(bf16 xwP, int2 csr) + relu + @w2 -> packed bf16 hP.
// 512 threads; warp handles 2 nodes; edge loop unrolled x2 for MLP.
// Tail re-zeros deg/cur for the next replay.
// ---------------------------------------------------------------------------
__global__ __launch_bounds__(512) void k_gather_mm(const int* __restrict__ off,
                                                   const int2* __restrict__ csr,
                                                   const uint32_t* __restrict__ xwP,
                                                   const float* __restrict__ dinv,
                                                   const float* __restrict__ b1,
                                                   const float* __restrict__ w2,
                                                   uint32_t* __restrict__ outP,
                                                   int* __restrict__ deg_z,
                                                   int* __restrict__ cur_z) {
    __shared__ float sw[64 * 64];
    __shared__ float sv[32][66];
    int tid = threadIdx.x;
    for (int i = tid; i < 64 * 64; i += 512) sw[i] = w2[i];
    int warp = tid >> 5;
    int lane = tid & 31;
    int c0 = lane * 2;
    float2 bb = *(const float2*)&b1[c0];
#pragma unroll
    for (int half = 0; half < 2; ++half) {
        int d = blockIdx.x * 32 + half * 16 + warp;
        float dv = dinv[d];
        float2 self = unpack_bf16x2(xwP[(size_t)d * GNN_HP + lane]);
        float accx = self.x * dv * dv + bb.x;
        float accy = self.y * dv * dv + bb.y;
        int e0 = off[d], e1 = off[d + 1];
        int e = e0;
        for (; e + 2 <= e1; e += 2) {
            int2 r0 = csr[e];
            int2 r1 = csr[e + 1];
            uint32_t v0 = xwP[(size_t)r0.x * GNN_HP + lane];
            uint32_t v1 = xwP[(size_t)r1.x * GNN_HP + lane];
            float n0 = __int_as_float(r0.y);
            float n1 = __int_as_float(r1.y);
            float2 u0 = unpack_bf16x2(v0);
            float2 u1 = unpack_bf16x2(v1);
            accx = fmaf(u0.x, n0, accx); accy = fmaf(u0.y, n0, accy);
            accx = fmaf(u1.x, n1, accx); accy = fmaf(u1.y, n1, accy);
        }
        if (e < e1) {
            int2 r0 = csr[e];
            float n0 = __int_as_float(r0.y);
            float2 u0 = unpack_bf16x2(xwP[(size_t)r0.x * GNN_HP + lane]);
            accx = fmaf(u0.x, n0, accx); accy = fmaf(u0.y, n0, accy);
        }
        sv[half * 16 + warp][c0]     = fmaxf(accx, 0.f);
        sv[half * 16 + warp][c0 + 1] = fmaxf(accy, 0.f);
    }
    __syncthreads();
#pragma unroll
    for (int half = 0; half < 2; ++half) {
        int r = half * 16 + warp;
        int d = blockIdx.x * 32 + r;
        float ox = 0.f, oy = 0.f;
#pragma unroll
        for (int k = 0; k < 64; ++k) {
            float a = sv[r][k];
            float2 wv = *(const float2*)&sw[k * 64 + c0];
            ox = fmaf(a, wv.x, ox);
            oy = fmaf(a, wv.y, oy);
        }
        outP[(size_t)d * GNN_HP + lane] = pack_bf16x2(ox, oy);
    }
    int zt = blockIdx.x * 512 + tid;
    if (zt < N_NODES) { deg_z[zt] = 0; cur_z[zt] = 0; }
}

// ---------------------------------------------------------------------------
// Gather layer 2: packed bf16 hP in, fp32 xw out (GEMM A); edge loop x2.
// ---------------------------------------------------------------------------
__global__ __launch_bounds__(256) void k_gather_p(const int* __restrict__ off,
                                                  const int2* __restrict__ csr,
                                                  const uint32_t* __restrict__ hP,
                                                  const float* __restrict__ dinv,
                                                  const float* __restrict__ bias,
                                                  float* __restrict__ out) {
    int warp = (blockIdx.x * 256 + threadIdx.x) >> 5;
    int lane = threadIdx.x & 31;
    if (warp >= N_NODES) return;
    int d = warp;
    int c0 = lane * 2;
    float dv = dinv[d];
    float2 self = unpack_bf16x2(hP[(size_t)d * GNN_HP + lane]);
    float2 bb   = *(const float2*)&bias[c0];
    float accx = self.x * dv * dv + bb.x;
    float accy = self.y * dv * dv + bb.y;
    int e0 = off[d], e1 = off[d + 1];
    int e = e0;
    for (; e + 2 <= e1; e += 2) {
        int2 r0 = csr[e];
        int2 r1 = csr[e + 1];
        uint32_t v0 = hP[(size_t)r0.x * GNN_HP + lane];
        uint32_t v1 = hP[(size_t)r1.x * GNN_HP + lane];
        float n0 = __int_as_float(r0.y);
        float n1 = __int_as_float(r1.y);
        float2 u0 = unpack_bf16x2(v0);
        float2 u1 = unpack_bf16x2(v1);
        accx = fmaf(u0.x, n0, accx); accy = fmaf(u0.y, n0, accy);
        accx = fmaf(u1.x, n1, accx); accy = fmaf(u1.y, n1, accy);
    }
    if (e < e1) {
        int2 r0 = csr[e];
        float n0 = __int_as_float(r0.y);
        float2 u0 = unpack_bf16x2(hP[(size_t)r0.x * GNN_HP + lane]);
        accx = fmaf(u0.x, n0, accx); accy = fmaf(u0.y, n0, accy);
    }
    float2 o; o.x = fmaxf(accx, 0.f); o.y = fmaxf(accy, 0.f);
    *(float2*)&out[(size_t)d * 64 + c0] = o;
}

// ---------------------------------------------------------------------------
// transpose with tf32 rounding
// ---------------------------------------------------------------------------
__global__ void k_transpose_tf32(const float* __restrict__ in, float* __restrict__ out,
                                 int R, int C) {
    int i = blockIdx.x * blockDim.x + threadIdx.x;
    if (i >= R * C) return;
    int r = i / C, c = i % C;
    out[c * R + r] = __uint_as_float(cvt_tf32(in[i]));
}

// whh [512,128] -> packed bf16x2 [64 kpairs][512 cols]
__global__ void k_pack_whh(const float* __restrict__ whh, uint32_t* __restrict__ out) {
    int i = blockIdx.x * blockDim.x + threadIdx.x;
    if (i >= (RNN_H / 2) * GATE4) return;
    int kp = i >> 9, col = i & 511;
    float lo = whh[col * RNN_H + 2 * kp];
    float hi = whh[col * RNN_H + 2 * kp + 1];
    out[i] = pack_bf16x2(lo, hi);
}

// ---------------------------------------------------------------------------
// tf32 GEMM: C[M, 256 packed] = bf16x2( A[M,K] @ Bt[K,512] + b1 + b2 )
// ---------------------------------------------------------------------------
__global__ __launch_bounds__(256) void k_gemm_tf32(const float* __restrict__ A,
                                                   const float* __restrict__ Bt,
                                                   const float* __restrict__ b1,
                                                   const float* __restrict__ b2,
                                                   uint32_t* __restrict__ C, int K) {
    __shared__ uint32_t As[16][72];
    __shared__ uint32_t Bs[16][136];
    int tid = threadIdx.x;
    int w = tid >> 5, lane = tid & 31;
    int mw = (w >> 2) * 32;
    int nw = (w & 3) * 32;
    int g = lane >> 2, t = lane & 3;
    size_t bm = (size_t)blockIdx.x * 64;
    int bn = blockIdx.y * 128;

    float acc[2][4][4];
#pragma unroll
    for (int mt = 0; mt < 2; ++mt)
#pragma unroll
        for (int nt = 0; nt < 4; ++nt)
#pragma unroll
            for (int i = 0; i < 4; ++i) acc[mt][nt][i] = 0.f;

    int ar = tid >> 2, ac = (tid & 3) * 4;
    int brw = tid >> 5, bcf = tid & 31;

    for (int k0 = 0; k0 < K; k0 += 16) {
        float4 av = *(const float4*)(A + (bm + ar) * K + k0 + ac);
        float4 bq0 = *(const float4*)(Bt + (size_t)(k0 + brw) * GATE4 + bn + bcf * 4);
        float4 bq1 = *(const float4*)(Bt + (size_t)(k0 + 8 + brw) * GATE4 + bn + bcf * 4);
        __syncthreads();
        As[ac + 0][ar] = cvt_tf32(av.x);
        As[ac + 1][ar] = cvt_tf32(av.y);
        As[ac + 2][ar] = cvt_tf32(av.z);
        As[ac + 3][ar] = cvt_tf32(av.w);
        {
            uint32_t* d0 = &Bs[brw][bcf * 4];
            d0[0] = __float_as_uint(bq0.x); d0[1] = __float_as_uint(bq0.y);
            d0[2] = __float_as_uint(bq0.z); d0[3] = __float_as_uint(bq0.w);
            uint32_t* d1 = &Bs[brw + 8][bcf * 4];
            d1[0] = __float_as_uint(bq1.x); d1[1] = __float_as_uint(bq1.y);
            d1[2] = __float_as_uint(bq1.z); d1[3] = __float_as_uint(bq1.w);
        }
        __syncthreads();
#pragma unroll
        for (int kt = 0; kt < 2; ++kt) {
            uint32_t af[2][4];
#pragma unroll
            for (int mt = 0; mt < 2; ++mt) {
                int mrow = mw + mt * 16 + g;
                af[mt][0] = As[kt * 8 + t][mrow];
                af[mt][1] = As[kt * 8 + t][mrow + 8];
                af[mt][2] = As[kt * 8 + t + 4][mrow];
                af[mt][3] = As[kt * 8 + t + 4][mrow + 8];
            }
#pragma unroll
            for (int nt = 0; nt < 4; ++nt) {
                int ncol = nw + nt * 8 + g;
                uint32_t bf0 = Bs[kt * 8 + t][ncol];
                uint32_t bf1 = Bs[kt * 8 + t + 4][ncol];
#pragma unroll
                for (int mt = 0; mt < 2; ++mt)
                    mma_tf32(acc[mt][nt][0], acc[mt][nt][1], acc[mt][nt][2], acc[mt][nt][3],
                             af[mt][0], af[mt][1], af[mt][2], af[mt][3], bf0, bf1);
            }
        }
    }
#pragma unroll
    for (int nt = 0; nt < 4; ++nt) {
        int c0 = bn + nw + nt * 8 + 2 * t;
        int jp = c0 >> 1;
        float bb0 = b1[c0] + b2[c0];
        float bb1 = b1[c0 + 1] + b2[c0 + 1];
#pragma unroll
        for (int mt = 0; mt < 2; ++mt) {
            size_t r0 = bm + mw + mt * 16 + g;
            C[r0 * GATE4P + jp]       = pack_bf16x2(acc[mt][nt][0] + bb0, acc[mt][nt][1] + bb1);
            C[(r0 + 8) * GATE4P + jp] = pack_bf16x2(acc[mt][nt][2] + bb0, acc[mt][nt][3] + bb1);
        }
    }
}

// ---------------------------------------------------------------------------
// Persistent bf16-mma LSTM, resident weights, packed bf16 pre, pipelined loads.
// 128 blocks x 512 threads, SBM=16.
// ---------------------------------------------------------------------------
#define L_SBM 16
#define L_NBLK (BATCH / L_SBM)     // 128
#define SH2 68
#define BSP 520
#define L_SMEM ((L_SBM * SH2 + 64 * BSP) * 4)   // 137,472 B

__global__ __launch_bounds__(512, 1) void k_lstm_mma(const uint32_t* __restrict__ pre,
                                                     const uint32_t* __restrict__ whhP,
                                                     float* __restrict__ hseq,
                                                     float* __restrict__ hlast) {
    extern __shared__ uint32_t smem[];
    uint32_t* sh = smem;
    uint32_t* Bs = smem + L_SBM * SH2;
    int tid = threadIdx.x;
    int w = tid >> 5, lane = tid & 31;
    int q = w;
    int g = lane >> 2, t = lane & 3;
    int b0 = blockIdx.x * L_SBM;

    uint32_t bs0 = (uint32_t)__cvta_generic_to_shared(Bs);

#pragma unroll
    for (int it = 0; it < 16; ++it) {
        int fid = it * 512 + tid;
        int row = fid >> 7, colf = fid & 127;
        CP_ASYNC16(bs0 + (uint32_t)(row * BSP + colf * 4) * 4,
                   whhP + (size_t)row * GATE4 + colf * 4);
    }
    CP_COMMIT();

    size_t preoff[8];
#pragma unroll
    for (int gate = 0; gate < 4; ++gate) {
        int jp = gate * 64 + q * 4 + t;
        preoff[gate * 2 + 0] = (size_t)(b0 + g) * SEQ_LEN * GATE4P + jp;
        preoff[gate * 2 + 1] = (size_t)(b0 + g + 8) * SEQ_LEN * GATE4P + jp;
    }

    float c[4];
#pragma unroll
    for (int i = 0; i < 4; ++i) c[i] = 0.f;
    for (int i = tid; i < L_SBM * SH2; i += 512) sh[i] = 0u;

    uint32_t pr[8];
#pragma unroll
    for (int i = 0; i < 8; ++i) pr[i] = pre[preoff[i]];

    CP_WAIT0();
    __syncthreads();

    for (int st = 0; st < SEQ_LEN; ++st) {
        float acc[4][4];
#pragma unroll
        for (int gate = 0; gate < 4; ++gate) {
            float2 p0 = unpack_bf16x2(pr[gate * 2 + 0]);
            float2 p1 = unpack_bf16x2(pr[gate * 2 + 1]);
            acc[gate][0] = p0.x; acc[gate][1] = p0.y;
            acc[gate][2] = p1.x; acc[gate][3] = p1.y;
        }
        if (st + 1 < SEQ_LEN) {
            size_t so = (size_t)(st + 1) * GATE4P;
#pragma unroll
            for (int i = 0; i < 8; ++i) pr[i] = pre[preoff[i] + so];
        }
#pragma unroll
        for (int kt = 0; kt < 8; ++kt) {
            int kp = kt * 8;
            uint32_t a0 = sh[g * SH2 + kp + t];
            uint32_t a1 = sh[(g + 8) * SH2 + kp + t];
            uint32_t a2 = sh[g * SH2 + kp + t + 4];
            uint32_t a3 = sh[(g + 8) * SH2 + kp + t + 4];
#pragma unroll
            for (int gate = 0; gate < 4; ++gate) {
                int colg = gate * 128 + q * 8 + g;
                uint32_t bf0 = Bs[(kp + t) * BSP + colg];
                uint32_t bf1 = Bs[(kp + t + 4) * BSP + colg];
                mma_bf16(acc[gate][0], acc[gate][1], acc[gate][2], acc[gate][3],
                         a0, a1, a2, a3, bf0, bf1);
            }
        }
        __syncthreads();
        float hv[4];
#pragma unroll
        for (int p = 0; p < 4; ++p) {
            float ig = sigmoid_fast(acc[0][p]);
            float fg = sigmoid_fast(acc[1][p]);
            float gg = tanh_fast(acc[2][p]);
            float og = sigmoid_fast(acc[3][p]);
            float cc = fg * c[p] + ig * gg;
            hv[p] = og * tanh_fast(cc);
            c[p] = cc;
        }
        int jp = q * 4 + t;
        sh[g * SH2 + jp]       = pack_bf16x2(hv[0], hv[1]);
        sh[(g + 8) * SH2 + jp] = pack_bf16x2(hv[2], hv[3]);
        int j0 = q * 8 + 2 * t;
        if (hseq) {
            float2 v0; v0.x = hv[0]; v0.y = hv[1];
            float2 v1; v1.x = hv[2]; v1.y = hv[3];
            *(float2*)(hseq + ((size_t)(b0 + g) * SEQ_LEN + st) * RNN_H + j0)     = v0;
            *(float2*)(hseq + ((size_t)(b0 + g + 8) * SEQ_LEN + st) * RNN_H + j0) = v1;
        }
        if (st == SEQ_LEN - 1) {
            float2 v0; v0.x = hv[0]; v0.y = hv[1];
            float2 v1; v1.x = hv[2]; v1.y = hv[3];
            *(float2*)(hlast + (b0 + g) * RNN_H + j0)     = v0;
            *(float2*)(hlast + (b0 + g + 8) * RNN_H + j0) = v1;
        }
        __syncthreads();
    }
}

// ---------------------------------------------------------------------------
// FC head
// ---------------------------------------------------------------------------
__global__ void k_fc(const float* __restrict__ h, const float* __restrict__ w,
                     const float* __restrict__ b, float* __restrict__ out) {
    int i = blockIdx.x * blockDim.x + threadIdx.x;
    if (i >= BATCH * OUT_DIM) return;
    int bb = i / OUT_DIM, o = i % OUT_DIM;
    float acc = b[o];
#pragma unroll 4
    for (int k = 0; k < RNN_H; ++k)
        acc = fmaf(h[bb * RNN_H + k], w[k * OUT_DIM + o], acc);
    out[i] = acc;
}

// ---------------------------------------------------------------------------
// Host launcher
// ---------------------------------------------------------------------------
extern "C" void kernel_launch(void* const* d_in, const int* in_sizes, int n_in,
                              void* d_out, int out_size) {
    const float* x  = (const float*)d_in[0];
    const int*   ei = (const int*)d_in[1];
    int w1i = n_in - 14;
    const float* w1   = (const float*)d_in[w1i + 0];
    const float* b1   = (const float*)d_in[w1i + 1];
    const float* w2   = (const float*)d_in[w1i + 2];
    const float* b2   = (const float*)d_in[w1i + 3];
    const float* wih0 = (const float*)d_in[w1i + 4];
    const float* whh0 = (const float*)d_in[w1i + 5];
    const float* bih0 = (const float*)d_in[w1i + 6];
    const float* bhh0 = (const float*)d_in[w1i + 7];
    const float* wih1 = (const float*)d_in[w1i + 8];
    const float* whh1 = (const float*)d_in[w1i + 9];
    const float* bih1 = (const float*)d_in[w1i + 10];
    const float* bhh1 = (const float*)d_in[w1i + 11];
    const float* fcw  = (const float*)d_in[w1i + 12];
    const float* fcb  = (const float*)d_in[w1i + 13];
    float* out = (float*)d_out;

    float *dinv, *xw, *hseq, *hstate;
    float *wihT0, *wihT1;
    uint32_t *xwP, *hP, *pre, *whhP0, *whhP1;
    int *deg, *cur, *off, *boff;
    int2 *csr;
    cudaGetSymbolAddress((void**)&dinv,    g_dinv);
    cudaGetSymbolAddress((void**)&deg,     g_deg);
    cudaGetSymbolAddress((void**)&cur,     g_cur);
    cudaGetSymbolAddress((void**)&off,     g_off);
    cudaGetSymbolAddress((void**)&boff,    g_boff);
    cudaGetSymbolAddress((void**)&csr,     g_csr);
    cudaGetSymbolAddress((void**)&xwP,     g_xwP);
    cudaGetSymbolAddress((void**)&hP,      g_hP);
    cudaGetSymbolAddress((void**)&xw,      g_xw);
    cudaGetSymbolAddress((void**)&pre,     g_pre);
    cudaGetSymbolAddress((void**)&hseq,    g_hseq);
    cudaGetSymbolAddress((void**)&hstate,  g_hstate);
    cudaGetSymbolAddress((void**)&wihT0,   g_wihT0);
    cudaGetSymbolAddress((void**)&wihT1,   g_wihT1);
    cudaGetSymbolAddress((void**)&whhP0,   g_whhP0);
    cudaGetSymbolAddress((void**)&whhP1,   g_whhP1);

    static cudaStream_t s1 = nullptr;
    static cudaEvent_t evFork = nullptr, evCsr = nullptr;
    static bool init_done = false;
    if (!init_done) {
        cudaFuncSetAttribute(k_lstm_mma, cudaFuncAttributeMaxDynamicSharedMemorySize, L_SMEM);
        cudaStreamCreateWithFlags(&s1, cudaStreamNonBlocking);
        cudaEventCreateWithFlags(&evFork, cudaEventDisableTiming);
        cudaEventCreateWithFlags(&evCsr,  cudaEventDisableTiming);
        init_done = true;
    }

    const int T = 256;

    // --- fork: CSR chain on s1 ---
    cudaEventRecord(evFork, 0);
    cudaStreamWaitEvent(s1, evFork, 0);
    k_deg_int<<<(N_EDGES + T - 1) / T, T, 0, s1>>>(ei, deg);
    k_dinv_bsum<<<SCAN_NB, SCAN_T, 0, s1>>>(deg, dinv, boff);
    k_scan_write2<<<SCAN_NB, SCAN_T, 0, s1>>>(deg, boff, off);
    k_csr_fill<<<(N_EDGES + T - 1) / T, T, 0, s1>>>(ei, off, cur, dinv, csr);
    cudaEventRecord(evCsr, s1);

    // --- main: dense GCN-1 + ALL weight prep (fills the CSR wait window) ---
    k_gcn_mm_p<<<N_NODES / 16, 512>>>(x, w1, xwP);
    k_transpose_tf32<<<(GATE4 * GNN_H + T - 1) / T, T>>>(wih0, wihT0, GATE4, GNN_H);
    k_transpose_tf32<<<(GATE4 * RNN_H + T - 1) / T, T>>>(wih1, wihT1, GATE4, RNN_H);
    k_pack_whh<<<((RNN_H / 2) * GATE4 + T - 1) / T, T>>>(whh0, whhP0);
    k_pack_whh<<<((RNN_H / 2) * GATE4 + T - 1) / T, T>>>(whh1, whhP1);

    // --- join, then gathers ---
    cudaStreamWaitEvent(0, evCsr, 0);
    k_gather_mm<<<N_NODES / 32, 512>>>(off, csr, xwP, dinv, b1, w2, hP, deg, cur);
    k_gather_p<<<N_NODES / 8, 256>>>(off, csr, hP, dinv, b2, xw);

    // --- LSTM layer 0 ---
    {
        dim3 grid(N_NODES / 64, GATE4 / 128);
        k_gemm_tf32<<<grid, 256>>>(xw, wihT0, bih0, bhh0, pre, GNN_H);
    }
    k_lstm_mma<<<L_NBLK, 512, L_SMEM>>>(pre, whhP0, hseq, hstate);

    // --- LSTM layer 1 ---
    {
        dim3 grid(N_NODES / 64, GATE4 / 128);
        k_gemm_tf32<<<grid, 256>>>(hseq, wihT1, bih1, bhh1, pre, RNN_H);
    }
    k_lstm_mma<<<L_NBLK, 512, L_SMEM>>>(pre, whhP1, (float*)nullptr, hstate);

    // --- FC head ---
    k_fc<<<(BATCH * OUT_DIM + T - 1) / T, T>>>(hstate, fcw, fcb, out);
}